// round 5
// baseline (speedup 1.0000x reference)
#include <cuda_runtime.h>
#include <cstdint>

// ---------------------------------------------------------------------------
// 4-layer LSTM (B=128, T=1024, D=128, H=[100,100,200,200]) + dense head.
// R4: f32x2 packed FFMA (fma.rn.f32x2) everywhere; double-buffered GEMM;
// float4 partial-reduce layouts; zx software prefetch; fast tanh via __expf.
// ---------------------------------------------------------------------------

#define TLEN 1024
#define BSZ  128
#define HPAD 256

typedef unsigned long long u64;

__device__ float g_zx[(size_t)BSZ * TLEN * 800];  // precomputed x@Wx+b
__device__ float g_seq[(size_t)BSZ * TLEN * 200]; // layer output sequence
__device__ float g_hbuf[BSZ * HPAD];              // final h for dense head

#define FMA2(d, a, b, c) \
    asm("fma.rn.f32x2 %0, %1, %2, %3;" : "=l"(d) : "l"(a), "l"(b), "l"(c))

__device__ __forceinline__ u64 pack2(float lo, float hi) {
    u64 d;
    asm("mov.b64 %0, {%1, %2};" : "=l"(d)
        : "r"(__float_as_uint(lo)), "r"(__float_as_uint(hi)));
    return d;
}
__device__ __forceinline__ float2 unpack2(u64 v) {
    unsigned lo, hi;
    asm("mov.b64 {%0, %1}, %2;" : "=r"(lo), "=r"(hi) : "l"(v));
    return make_float2(__uint_as_float(lo), __uint_as_float(hi));
}

__device__ __forceinline__ float sigm(float x) {
    return __fdividef(1.0f, 1.0f + __expf(-x));
}
__device__ __forceinline__ float tanh_fast(float x) {
    return 1.0f - __fdividef(2.0f, __expf(2.0f * x) + 1.0f);
}

// ---------------------------------------------------------------------------
// Precompute GEMM: C[M=BSZ*TLEN, N] = A[M, K] @ W[K, N] + bias -> g_zx.
// 128x128 CTA tile, 256 threads, 8x8 thread tile (m-paired f32x2 FFMA),
// KC=8 double-buffered smem with register prefetch.
// ---------------------------------------------------------------------------
template <int K>
__global__ void __launch_bounds__(256, 2)
gemm_x(const float* __restrict__ Ain, const float* __restrict__ W,
       const float* __restrict__ bias, int N, int use_seq)
{
    constexpr int KC = 8;
    constexpr int NCHUNK = (K + KC - 1) / KC;

    __shared__ __align__(16) float A_s[2][KC][132];
    __shared__ __align__(16) float W_s[2][KC][132];

    const float* __restrict__ A = use_seq ? g_seq : Ain;
    const int tid = threadIdx.x;
    const int tx = tid & 15, ty = tid >> 4;
    const int m0 = blockIdx.y * 128, n0 = blockIdx.x * 128;

    const int a_row = tid >> 3, a_kk = tid & 7;       // + 32*e rows
    const int w_kk0 = tid >> 7, w_n = tid & 127;      // kk = 2e + w_kk0

    float aR[4], wR[4];

    auto ldA = [&](int c) {
        const int k0 = c * KC;
        #pragma unroll
        for (int e = 0; e < 4; ++e) {
            int row = a_row + 32 * e;
            aR[e] = (k0 + a_kk < K) ? A[(size_t)(m0 + row) * K + k0 + a_kk] : 0.0f;
        }
    };
    auto ldW = [&](int c) {
        const int k0 = c * KC;
        #pragma unroll
        for (int e = 0; e < 4; ++e) {
            int kk = 2 * e + w_kk0;
            float v = 0.0f;
            if ((k0 + kk < K) && (n0 + w_n < N)) v = W[(size_t)(k0 + kk) * N + n0 + w_n];
            wR[e] = v;
        }
    };
    auto stA = [&](int buf) {
        #pragma unroll
        for (int e = 0; e < 4; ++e) A_s[buf][a_kk][a_row + 32 * e] = aR[e];
    };
    auto stW = [&](int buf) {
        #pragma unroll
        for (int e = 0; e < 4; ++e) W_s[buf][2 * e + w_kk0][w_n] = wR[e];
    };

    ldA(0); ldW(0);
    stA(0); stW(0);
    __syncthreads();

    u64 acc2[4][8];
    #pragma unroll
    for (int mp = 0; mp < 4; ++mp)
        #pragma unroll
        for (int j = 0; j < 8; ++j) acc2[mp][j] = 0ull;

    for (int c = 0; c < NCHUNK; ++c) {
        const int buf = c & 1;
        if (c + 1 < NCHUNK) { ldA(c + 1); ldW(c + 1); }
        #pragma unroll
        for (int k = 0; k < KC; ++k) {
            ulonglong2 ap0 = *reinterpret_cast<const ulonglong2*>(&A_s[buf][k][ty * 8]);
            ulonglong2 ap1 = *reinterpret_cast<const ulonglong2*>(&A_s[buf][k][ty * 8 + 4]);
            float4 w0 = *reinterpret_cast<const float4*>(&W_s[buf][k][tx * 8]);
            float4 w1 = *reinterpret_cast<const float4*>(&W_s[buf][k][tx * 8 + 4]);
            u64 ap[4] = {ap0.x, ap0.y, ap1.x, ap1.y};
            u64 wd[8];
            wd[0] = pack2(w0.x, w0.x); wd[1] = pack2(w0.y, w0.y);
            wd[2] = pack2(w0.z, w0.z); wd[3] = pack2(w0.w, w0.w);
            wd[4] = pack2(w1.x, w1.x); wd[5] = pack2(w1.y, w1.y);
            wd[6] = pack2(w1.z, w1.z); wd[7] = pack2(w1.w, w1.w);
            #pragma unroll
            for (int mp = 0; mp < 4; ++mp)
                #pragma unroll
                for (int j = 0; j < 8; ++j)
                    FMA2(acc2[mp][j], ap[mp], wd[j], acc2[mp][j]);
        }
        if (c + 1 < NCHUNK) { stA(buf ^ 1); stW(buf ^ 1); }
        __syncthreads();
    }

    // unpack + bias + store
    float accf[8][8];
    #pragma unroll
    for (int mp = 0; mp < 4; ++mp)
        #pragma unroll
        for (int j = 0; j < 8; ++j) {
            float2 t = unpack2(acc2[mp][j]);
            accf[2 * mp][j]     = t.x;
            accf[2 * mp + 1][j] = t.y;
        }

    if (n0 + tx * 8 < N) {
        float b[8];
        #pragma unroll
        for (int j = 0; j < 8; ++j) b[j] = bias[n0 + tx * 8 + j];
        #pragma unroll
        for (int i = 0; i < 8; ++i) {
            size_t off = (size_t)(m0 + ty * 8 + i) * N + (n0 + tx * 8);
            float4 v0 = make_float4(accf[i][0] + b[0], accf[i][1] + b[1],
                                    accf[i][2] + b[2], accf[i][3] + b[3]);
            float4 v1 = make_float4(accf[i][4] + b[4], accf[i][5] + b[5],
                                    accf[i][6] + b[6], accf[i][7] + b[7]);
            *reinterpret_cast<float4*>(&g_zx[off])     = v0;
            *reinterpret_cast<float4*>(&g_zx[off + 4]) = v1;
        }
    }
}

// ---------------------------------------------------------------------------
// H=100 scan: 1 CTA per batch row. Wh in regs (k-paired f32x2), h in SMEM.
// Thread (s=tid/100, j=tid%100) accumulates k = s*20..s*20+19 for column j.
// ---------------------------------------------------------------------------
__global__ void __launch_bounds__(512, 1)
scan100(const float* __restrict__ Wh)
{
    __shared__ __align__(16) float h_s[104];
    __shared__ __align__(16) float zp[5][100][4];

    const int tid = threadIdx.x;
    const int b   = blockIdx.x;
    const int s   = tid / 100;
    const int j   = tid % 100;
    const bool gemm_act = (tid < 500);
    const bool red_act  = (tid < 100);

    u64 w2[10][4];   // [k-pair][gate] = {W[k],W[k+1]}
    if (gemm_act) {
        const int k0 = s * 20;
        #pragma unroll
        for (int kp = 0; kp < 10; ++kp) {
            #pragma unroll
            for (int g = 0; g < 4; ++g) {
                float wlo = Wh[(k0 + 2 * kp)     * 400 + g * 100 + j];
                float whi = Wh[(k0 + 2 * kp + 1) * 400 + g * 100 + j];
                w2[kp][g] = pack2(wlo, whi);
            }
        }
    }
    if (red_act) h_s[j] = 0.0f;
    float c = 0.0f;
    __syncthreads();

    const float* __restrict__ zbase = g_zx + (size_t)b * TLEN * 400;
    float* __restrict__ ybase = g_seq + (size_t)b * TLEN * 100;

    float zx0 = 0.f, zx1 = 0.f, zx2 = 0.f, zx3 = 0.f;
    if (red_act) {
        zx0 = zbase[j]; zx1 = zbase[100 + j];
        zx2 = zbase[200 + j]; zx3 = zbase[300 + j];
    }

    for (int t = 0; t < TLEN; ++t) {
        float nx0 = 0.f, nx1 = 0.f, nx2 = 0.f, nx3 = 0.f;
        if (red_act && (t + 1 < TLEN)) {      // prefetch next step's zx
            const float* zr = zbase + (size_t)(t + 1) * 400;
            nx0 = zr[j]; nx1 = zr[100 + j]; nx2 = zr[200 + j]; nx3 = zr[300 + j];
        }
        if (gemm_act) {
            u64 a0 = 0ull, a1 = 0ull, a2 = 0ull, a3 = 0ull;
            const ulonglong2* hp = reinterpret_cast<const ulonglong2*>(h_s + s * 20);
            #pragma unroll
            for (int q = 0; q < 5; ++q) {
                ulonglong2 hv = hp[q];        // {h[k],h[k+1]} , {h[k+2],h[k+3]}
                FMA2(a0, hv.x, w2[2 * q][0], a0);
                FMA2(a1, hv.x, w2[2 * q][1], a1);
                FMA2(a2, hv.x, w2[2 * q][2], a2);
                FMA2(a3, hv.x, w2[2 * q][3], a3);
                FMA2(a0, hv.y, w2[2 * q + 1][0], a0);
                FMA2(a1, hv.y, w2[2 * q + 1][1], a1);
                FMA2(a2, hv.y, w2[2 * q + 1][2], a2);
                FMA2(a3, hv.y, w2[2 * q + 1][3], a3);
            }
            float2 p0 = unpack2(a0), p1 = unpack2(a1), p2 = unpack2(a2), p3 = unpack2(a3);
            float4 v = make_float4(p0.x + p0.y, p1.x + p1.y, p2.x + p2.y, p3.x + p3.y);
            *reinterpret_cast<float4*>(&zp[s][j][0]) = v;
        }
        __syncthreads();
        if (red_act) {
            float4 z = *reinterpret_cast<const float4*>(&zp[0][j][0]);
            float z0 = zx0 + z.x, z1 = zx1 + z.y, z2 = zx2 + z.z, z3 = zx3 + z.w;
            #pragma unroll
            for (int ss = 1; ss < 5; ++ss) {
                float4 p = *reinterpret_cast<const float4*>(&zp[ss][j][0]);
                z0 += p.x; z1 += p.y; z2 += p.z; z3 += p.w;
            }
            float gi = sigm(z0), gf = sigm(z1), gg = tanh_fast(z2), go = sigm(z3);
            c = gf * c + gi * gg;
            float h = go * tanh_fast(c);
            h_s[j] = h;
            ybase[(size_t)t * 100 + j] = h;
        }
        zx0 = nx0; zx1 = nx1; zx2 = nx2; zx3 = nx3;
        __syncthreads();
    }
}

// ---------------------------------------------------------------------------
// H=200 scan: cluster of 4 CTAs; rank owns j-slice [50r, 50r+50); cluster owns
// 4 batch rows. Wh slice in regs (gate-paired f32x2); h via DSMEM broadcast.
// ---------------------------------------------------------------------------
template <int WRITE_Y>
__global__ void __launch_bounds__(512, 1) __cluster_dims__(4, 1, 1)
scan200(const float* __restrict__ Wh)
{
    __shared__ __align__(16) float h_s[2][200 * 4];   // [buf][jg][row] float4 per jg
    __shared__ __align__(16) float zp[10][4][50][4];  // [split][row][jl][gate]

    const int tid = threadIdx.x;
    uint32_t rank;
    asm("mov.u32 %0, %%cluster_ctarank;" : "=r"(rank));
    const int cl = blockIdx.x >> 2;

    const int s  = tid / 50;              // gemm split 0..9 (tid<500)
    const int jl = tid % 50;
    const bool gemm_act = (tid < 500);
    const bool red_act  = (tid < 200);    // reduce row = s (0..3)
    const int  rr = s;
    const int  jg = (int)rank * 50 + jl;

    uint32_t hs_addr;
    {
        const void* p = (const void*)&h_s[0][0];
        asm("{ .reg .u64 t; cvta.to.shared.u64 t, %1; cvt.u32.u64 %0, t; }"
            : "=r"(hs_addr) : "l"(p));
    }

    // w2[k][gp] = {W[k][gate 2gp], W[k][gate 2gp+1]} for col jg
    u64 w2[20][2];
    if (gemm_act) {
        const int k0 = s * 20;
        #pragma unroll
        for (int kk = 0; kk < 20; ++kk) {
            const int k = k0 + kk;
            w2[kk][0] = pack2(Wh[k * 800 + 0 * 200 + jg], Wh[k * 800 + 1 * 200 + jg]);
            w2[kk][1] = pack2(Wh[k * 800 + 2 * 200 + jg], Wh[k * 800 + 3 * 200 + jg]);
        }
    }
    for (int i = tid; i < 2 * 800; i += 512) h_s[0][i] = 0.0f;
    float c = 0.0f;
    __syncthreads();
    asm volatile("barrier.cluster.arrive.aligned;" ::: "memory");
    asm volatile("barrier.cluster.wait.aligned;" ::: "memory");

    const int b = cl * 4 + rr;
    const float* __restrict__ zbase = g_zx + (size_t)b * TLEN * 800;
    float* __restrict__ ybase = g_seq + (size_t)b * TLEN * 200;

    float zx0 = 0.f, zx1 = 0.f, zx2 = 0.f, zx3 = 0.f;
    if (red_act) {
        zx0 = zbase[jg]; zx1 = zbase[200 + jg];
        zx2 = zbase[400 + jg]; zx3 = zbase[600 + jg];
    }

    for (int t = 0; t < TLEN; ++t) {
        const int cur = t & 1, nxt = cur ^ 1;

        float nx0 = 0.f, nx1 = 0.f, nx2 = 0.f, nx3 = 0.f;
        if (red_act && (t + 1 < TLEN)) {
            const float* zr = zbase + (size_t)(t + 1) * 800;
            nx0 = zr[jg]; nx1 = zr[200 + jg]; nx2 = zr[400 + jg]; nx3 = zr[600 + jg];
        }

        if (gemm_act) {
            u64 acc[4][2];   // [row][gate-pair]
            #pragma unroll
            for (int r2 = 0; r2 < 4; ++r2) { acc[r2][0] = 0ull; acc[r2][1] = 0ull; }

            const float4* hp = reinterpret_cast<const float4*>(h_s[cur]);
            const int k0 = s * 20;
            #pragma unroll
            for (int kk = 0; kk < 20; ++kk) {
                float4 xv = hp[k0 + kk];
                u64 xd0 = pack2(xv.x, xv.x);
                u64 xd1 = pack2(xv.y, xv.y);
                u64 xd2 = pack2(xv.z, xv.z);
                u64 xd3 = pack2(xv.w, xv.w);
                FMA2(acc[0][0], xd0, w2[kk][0], acc[0][0]);
                FMA2(acc[0][1], xd0, w2[kk][1], acc[0][1]);
                FMA2(acc[1][0], xd1, w2[kk][0], acc[1][0]);
                FMA2(acc[1][1], xd1, w2[kk][1], acc[1][1]);
                FMA2(acc[2][0], xd2, w2[kk][0], acc[2][0]);
                FMA2(acc[2][1], xd2, w2[kk][1], acc[2][1]);
                FMA2(acc[3][0], xd3, w2[kk][0], acc[3][0]);
                FMA2(acc[3][1], xd3, w2[kk][1], acc[3][1]);
            }
            #pragma unroll
            for (int r2 = 0; r2 < 4; ++r2) {
                float2 pif = unpack2(acc[r2][0]);
                float2 pgo = unpack2(acc[r2][1]);
                *reinterpret_cast<float4*>(&zp[s][r2][jl][0]) =
                    make_float4(pif.x, pif.y, pgo.x, pgo.y);
            }
        }
        __syncthreads();

        if (red_act) {
            float4 z = *reinterpret_cast<const float4*>(&zp[0][rr][jl][0]);
            float z0 = zx0 + z.x, z1 = zx1 + z.y, z2 = zx2 + z.z, z3 = zx3 + z.w;
            #pragma unroll
            for (int ss = 1; ss < 10; ++ss) {
                float4 p = *reinterpret_cast<const float4*>(&zp[ss][rr][jl][0]);
                z0 += p.x; z1 += p.y; z2 += p.z; z3 += p.w;
            }
            float gi = sigm(z0), gf = sigm(z1), gg = tanh_fast(z2), go = sigm(z3);
            c = gf * c + gi * gg;
            float h = go * tanh_fast(c);

            uint32_t laddr = hs_addr + (uint32_t)(nxt * 800 + jg * 4 + rr) * 4u;
            #pragma unroll
            for (int p = 0; p < 4; ++p) {
                uint32_t raddr;
                asm("mapa.shared::cluster.u32 %0, %1, %2;"
                    : "=r"(raddr) : "r"(laddr), "r"(p));
                asm volatile("st.shared::cluster.f32 [%0], %1;"
                             :: "r"(raddr), "f"(h) : "memory");
            }
            if (WRITE_Y) ybase[(size_t)t * 200 + jg] = h;
            if (t == TLEN - 1) g_hbuf[b * HPAD + jg] = h;
        }
        zx0 = nx0; zx1 = nx1; zx2 = nx2; zx3 = nx3;
        asm volatile("barrier.cluster.arrive.aligned;" ::: "memory");
        asm volatile("barrier.cluster.wait.aligned;" ::: "memory");
    }
}

// Final dense: out[b, o] = h_last[b, :200] @ Wd + bd.
__global__ void dense_kernel(const float* __restrict__ Wd,
                             const float* __restrict__ bd,
                             float* __restrict__ out)
{
    int idx = blockIdx.x * blockDim.x + threadIdx.x;
    if (idx >= BSZ * 6) return;
    int b = idx / 6, o = idx - b * 6;
    const float* h = g_hbuf + b * HPAD;
    float s = bd[o];
    #pragma unroll 8
    for (int k = 0; k < 200; ++k) s += h[k] * Wd[k * 6 + o];
    out[idx] = s;
}

extern "C" void kernel_launch(void* const* d_in, const int* in_sizes, int n_in,
                              void* d_out, int out_size)
{
    const float* xs  = (const float*)d_in[0];
    const float* Wx0 = (const float*)d_in[1];
    const float* Wh0 = (const float*)d_in[2];
    const float* b0  = (const float*)d_in[3];
    const float* Wx1 = (const float*)d_in[4];
    const float* Wh1 = (const float*)d_in[5];
    const float* b1  = (const float*)d_in[6];
    const float* Wx2 = (const float*)d_in[7];
    const float* Wh2 = (const float*)d_in[8];
    const float* b2  = (const float*)d_in[9];
    const float* Wx3 = (const float*)d_in[10];
    const float* Wh3 = (const float*)d_in[11];
    const float* b3  = (const float*)d_in[12];
    const float* Wd  = (const float*)d_in[13];
    const float* bd  = (const float*)d_in[14];

    const dim3 gN400(4, 1024);
    const dim3 gN800(7, 1024);

    // L0
    gemm_x<128><<<gN400, 256>>>(xs, Wx0, b0, 400, 0);
    scan100<<<BSZ, 512>>>(Wh0);
    // L1
    gemm_x<100><<<gN400, 256>>>(nullptr, Wx1, b1, 400, 1);
    scan100<<<BSZ, 512>>>(Wh1);
    // L2
    gemm_x<100><<<gN800, 256>>>(nullptr, Wx2, b2, 800, 1);
    scan200<1><<<BSZ, 512>>>(Wh2);
    // L3
    gemm_x<200><<<gN800, 256>>>(nullptr, Wx3, b3, 800, 1);
    scan200<0><<<BSZ, 512>>>(Wh3);
    // head
    dense_kernel<<<3, 256>>>(Wd, bd, (float*)d_out);
}

// round 6
// speedup vs baseline: 1.1410x; 1.1410x over previous
#include <cuda_runtime.h>
#include <cstdint>

// ---------------------------------------------------------------------------
// 4-layer LSTM (B=128, T=1024, D=128, H=[100,100,200,200]) + dense head.
// R5: gate-interleaved zx layout ([b][t][j][4]) -> scans read ONE float4/step
// with a 2-deep register prefetch ring (kills the DRAM stall); scan200 moved
// to k-pair FFMA2 packing (no dup-pack instructions). GEMMs permute W columns
// to produce the interleaved layout.
// ---------------------------------------------------------------------------

#define TLEN 1024
#define BSZ  128
#define HPAD 256

typedef unsigned long long u64;

__device__ float g_zx[(size_t)BSZ * TLEN * 800];  // x@Wx+b, layout [b][t][j][4]
__device__ float g_seq[(size_t)BSZ * TLEN * 200]; // layer output sequence
__device__ float g_hbuf[BSZ * HPAD];              // final h for dense head

#define FMA2(d, a, b, c) \
    asm("fma.rn.f32x2 %0, %1, %2, %3;" : "=l"(d) : "l"(a), "l"(b), "l"(c))

__device__ __forceinline__ u64 pack2(float lo, float hi) {
    u64 d;
    asm("mov.b64 %0, {%1, %2};" : "=l"(d)
        : "r"(__float_as_uint(lo)), "r"(__float_as_uint(hi)));
    return d;
}
__device__ __forceinline__ float2 unpack2(u64 v) {
    unsigned lo, hi;
    asm("mov.b64 {%0, %1}, %2;" : "=r"(lo), "=r"(hi) : "l"(v));
    return make_float2(__uint_as_float(lo), __uint_as_float(hi));
}

__device__ __forceinline__ float sigm(float x) {
    return __fdividef(1.0f, 1.0f + __expf(-x));
}
__device__ __forceinline__ float tanh_fast(float x) {
    return 1.0f - __fdividef(2.0f, __expf(2.0f * x) + 1.0f);
}

// ---------------------------------------------------------------------------
// Precompute GEMM: C[M=BSZ*TLEN, n] = A[M, K] @ W[K, colmap(n)] + bias.
// Output column n = j*4+g  <-  weight column g*Hn+j  (gate-interleaved zx).
// 128x128 CTA tile, 256 threads, 8x8 thread tile (m-paired f32x2 FFMA),
// KC=8 double-buffered smem with register prefetch.
// ---------------------------------------------------------------------------
template <int K>
__global__ void __launch_bounds__(256, 2)
gemm_x(const float* __restrict__ Ain, const float* __restrict__ W,
       const float* __restrict__ bias, int N, int Hn, int use_seq)
{
    constexpr int KC = 8;
    constexpr int NCHUNK = (K + KC - 1) / KC;

    __shared__ __align__(16) float A_s[2][KC][132];
    __shared__ __align__(16) float W_s[2][KC][132];

    const float* __restrict__ A = use_seq ? g_seq : Ain;
    const int tid = threadIdx.x;
    const int tx = tid & 15, ty = tid >> 4;
    const int m0 = blockIdx.y * 128, n0 = blockIdx.x * 128;

    const int a_row = tid >> 3, a_kk = tid & 7;
    const int w_kk0 = tid >> 7, w_n = tid & 127;
    const int wcol  = n0 + w_n;                      // output column
    const int wsrc  = (wcol & 3) * Hn + (wcol >> 2); // source W column

    float aR[4], wR[4];

    auto ldA = [&](int c) {
        const int k0 = c * KC;
        #pragma unroll
        for (int e = 0; e < 4; ++e) {
            int row = a_row + 32 * e;
            aR[e] = (k0 + a_kk < K) ? A[(size_t)(m0 + row) * K + k0 + a_kk] : 0.0f;
        }
    };
    auto ldW = [&](int c) {
        const int k0 = c * KC;
        #pragma unroll
        for (int e = 0; e < 4; ++e) {
            int kk = 2 * e + w_kk0;
            float v = 0.0f;
            if ((k0 + kk < K) && (wcol < N)) v = W[(size_t)(k0 + kk) * N + wsrc];
            wR[e] = v;
        }
    };
    auto stA = [&](int buf) {
        #pragma unroll
        for (int e = 0; e < 4; ++e) A_s[buf][a_kk][a_row + 32 * e] = aR[e];
    };
    auto stW = [&](int buf) {
        #pragma unroll
        for (int e = 0; e < 4; ++e) W_s[buf][2 * e + w_kk0][w_n] = wR[e];
    };

    ldA(0); ldW(0);
    stA(0); stW(0);
    __syncthreads();

    u64 acc2[4][8];
    #pragma unroll
    for (int mp = 0; mp < 4; ++mp)
        #pragma unroll
        for (int j = 0; j < 8; ++j) acc2[mp][j] = 0ull;

    for (int c = 0; c < NCHUNK; ++c) {
        const int buf = c & 1;
        if (c + 1 < NCHUNK) { ldA(c + 1); ldW(c + 1); }
        #pragma unroll
        for (int k = 0; k < KC; ++k) {
            ulonglong2 ap0 = *reinterpret_cast<const ulonglong2*>(&A_s[buf][k][ty * 8]);
            ulonglong2 ap1 = *reinterpret_cast<const ulonglong2*>(&A_s[buf][k][ty * 8 + 4]);
            float4 w0 = *reinterpret_cast<const float4*>(&W_s[buf][k][tx * 8]);
            float4 w1 = *reinterpret_cast<const float4*>(&W_s[buf][k][tx * 8 + 4]);
            u64 ap[4] = {ap0.x, ap0.y, ap1.x, ap1.y};
            u64 wd[8];
            wd[0] = pack2(w0.x, w0.x); wd[1] = pack2(w0.y, w0.y);
            wd[2] = pack2(w0.z, w0.z); wd[3] = pack2(w0.w, w0.w);
            wd[4] = pack2(w1.x, w1.x); wd[5] = pack2(w1.y, w1.y);
            wd[6] = pack2(w1.z, w1.z); wd[7] = pack2(w1.w, w1.w);
            #pragma unroll
            for (int mp = 0; mp < 4; ++mp)
                #pragma unroll
                for (int j = 0; j < 8; ++j)
                    FMA2(acc2[mp][j], ap[mp], wd[j], acc2[mp][j]);
        }
        if (c + 1 < NCHUNK) { stA(buf ^ 1); stW(buf ^ 1); }
        __syncthreads();
    }

    float accf[8][8];
    #pragma unroll
    for (int mp = 0; mp < 4; ++mp)
        #pragma unroll
        for (int j = 0; j < 8; ++j) {
            float2 t = unpack2(acc2[mp][j]);
            accf[2 * mp][j]     = t.x;
            accf[2 * mp + 1][j] = t.y;
        }

    if (n0 + tx * 8 < N) {
        float b[8];
        #pragma unroll
        for (int j = 0; j < 8; ++j) {
            int cc = n0 + tx * 8 + j;
            b[j] = bias[(cc & 3) * Hn + (cc >> 2)];
        }
        #pragma unroll
        for (int i = 0; i < 8; ++i) {
            size_t off = (size_t)(m0 + ty * 8 + i) * N + (n0 + tx * 8);
            float4 v0 = make_float4(accf[i][0] + b[0], accf[i][1] + b[1],
                                    accf[i][2] + b[2], accf[i][3] + b[3]);
            float4 v1 = make_float4(accf[i][4] + b[4], accf[i][5] + b[5],
                                    accf[i][6] + b[6], accf[i][7] + b[7]);
            *reinterpret_cast<float4*>(&g_zx[off])     = v0;
            *reinterpret_cast<float4*>(&g_zx[off + 4]) = v1;
        }
    }
}

// ---------------------------------------------------------------------------
// H=100 scan: 1 CTA per batch row. Wh in regs (k-paired f32x2), h in SMEM.
// zx: one float4 per thread per step, 2-deep register prefetch ring.
// ---------------------------------------------------------------------------
__global__ void __launch_bounds__(512, 1)
scan100(const float* __restrict__ Wh)
{
    __shared__ __align__(16) float  h_s[104];
    __shared__ __align__(16) float4 zp[5][100];

    const int tid = threadIdx.x;
    const int b   = blockIdx.x;
    const int s   = tid / 100;
    const int j   = tid % 100;
    const bool ga  = (tid < 500);
    const bool red = (tid < 100);

    u64 w2[10][4];
    if (ga) {
        const int k0 = s * 20;
        #pragma unroll
        for (int kp = 0; kp < 10; ++kp)
            #pragma unroll
            for (int g = 0; g < 4; ++g)
                w2[kp][g] = pack2(Wh[(k0 + 2 * kp)     * 400 + g * 100 + j],
                                  Wh[(k0 + 2 * kp + 1) * 400 + g * 100 + j]);
    }
    if (red) h_s[j] = 0.0f;
    float c = 0.0f;
    __syncthreads();

    const float* __restrict__ zbase = g_zx + (size_t)b * TLEN * 400;
    float* __restrict__ ybase = g_seq + (size_t)b * TLEN * 100;

    float4 zb0 = make_float4(0, 0, 0, 0), zb1 = zb0;
    if (red) {
        zb0 = *reinterpret_cast<const float4*>(zbase + j * 4);
        zb1 = *reinterpret_cast<const float4*>(zbase + 400 + j * 4);
    }

    auto step = [&](int t, float4& zslot) {
        float4 zc;
        if (red) {
            zc = zslot;
            int tp = (t + 2 < TLEN) ? t + 2 : t;
            zslot = *reinterpret_cast<const float4*>(zbase + (size_t)tp * 400 + j * 4);
        }
        if (ga) {
            u64 a0 = 0ull, a1 = 0ull, a2 = 0ull, a3 = 0ull;
            const ulonglong2* hp = reinterpret_cast<const ulonglong2*>(h_s);
            const int qb = s * 5;
            #pragma unroll
            for (int q = 0; q < 5; ++q) {
                ulonglong2 hv = hp[qb + q];
                FMA2(a0, hv.x, w2[2 * q][0], a0);
                FMA2(a1, hv.x, w2[2 * q][1], a1);
                FMA2(a2, hv.x, w2[2 * q][2], a2);
                FMA2(a3, hv.x, w2[2 * q][3], a3);
                FMA2(a0, hv.y, w2[2 * q + 1][0], a0);
                FMA2(a1, hv.y, w2[2 * q + 1][1], a1);
                FMA2(a2, hv.y, w2[2 * q + 1][2], a2);
                FMA2(a3, hv.y, w2[2 * q + 1][3], a3);
            }
            float2 p0 = unpack2(a0), p1 = unpack2(a1), p2 = unpack2(a2), p3 = unpack2(a3);
            zp[s][j] = make_float4(p0.x + p0.y, p1.x + p1.y, p2.x + p2.y, p3.x + p3.y);
        }
        __syncthreads();
        if (red) {
            float z0 = zc.x, z1 = zc.y, z2 = zc.z, z3 = zc.w;
            #pragma unroll
            for (int ss = 0; ss < 5; ++ss) {
                float4 p = zp[ss][j];
                z0 += p.x; z1 += p.y; z2 += p.z; z3 += p.w;
            }
            float gi = sigm(z0), gf = sigm(z1), gg = tanh_fast(z2), go = sigm(z3);
            c = gf * c + gi * gg;
            float h = go * tanh_fast(c);
            h_s[j] = h;
            ybase[(size_t)t * 100 + j] = h;
        }
        __syncthreads();
    };

    for (int t = 0; t < TLEN; t += 2) {
        step(t,     zb0);
        step(t + 1, zb1);
    }
}

// ---------------------------------------------------------------------------
// H=200 scan: cluster of 4 CTAs; rank owns j-slice [50r, 50r+50); cluster owns
// 4 batch rows. Wh slice in regs (k-paired f32x2, NO dup-packs); h double-
// buffered in SMEM, exchanged via DSMEM; zx via float4 + 2-deep prefetch.
// ---------------------------------------------------------------------------
template <int WRITE_Y>
__global__ void __launch_bounds__(512, 1) __cluster_dims__(4, 1, 1)
scan200(const float* __restrict__ Wh)
{
    __shared__ __align__(16) float  h_s[2][4][208];   // [buf][row][k]
    __shared__ __align__(16) float4 zp[10][4][50];    // [split][row][jl]

    const int tid = threadIdx.x;
    uint32_t rank;
    asm("mov.u32 %0, %%cluster_ctarank;" : "=r"(rank));
    const int cl = blockIdx.x >> 2;

    const int s  = tid / 50;               // gemm split 0..9 (tid<500)
    const int jl = tid % 50;
    const bool ga  = (tid < 500);
    const bool red = (tid < 200);          // reduce row = s (0..3)
    const int  rr  = s;
    const int  jg  = (int)rank * 50 + jl;

    uint32_t hs_addr;
    {
        const void* p = (const void*)&h_s[0][0][0];
        asm("{ .reg .u64 t; cvta.to.shared.u64 t, %1; cvt.u32.u64 %0, t; }"
            : "=r"(hs_addr) : "l"(p));
    }

    // k-paired weights: w2[kp][g] = {W[k][g][jg], W[k+1][g][jg]}
    u64 w2[10][4];
    if (ga) {
        const int k0 = s * 20;
        #pragma unroll
        for (int kp = 0; kp < 10; ++kp)
            #pragma unroll
            for (int g = 0; g < 4; ++g)
                w2[kp][g] = pack2(Wh[(k0 + 2 * kp)     * 800 + g * 200 + jg],
                                  Wh[(k0 + 2 * kp + 1) * 800 + g * 200 + jg]);
    }
    for (int i = tid; i < 2 * 4 * 208; i += 512) (&h_s[0][0][0])[i] = 0.0f;
    float c = 0.0f;
    __syncthreads();
    asm volatile("barrier.cluster.arrive.aligned;" ::: "memory");
    asm volatile("barrier.cluster.wait.aligned;" ::: "memory");

    const int b = cl * 4 + rr;
    const float* __restrict__ zbase = g_zx + (size_t)b * TLEN * 800;
    float* __restrict__ ybase = g_seq + (size_t)b * TLEN * 200;

    float4 zb0 = make_float4(0, 0, 0, 0), zb1 = zb0;
    if (red) {
        zb0 = *reinterpret_cast<const float4*>(zbase + jg * 4);
        zb1 = *reinterpret_cast<const float4*>(zbase + 800 + jg * 4);
    }

    auto step = [&](int t, float4& zslot, int cur) {
        float4 zc;
        if (red) {
            zc = zslot;
            int tp = (t + 2 < TLEN) ? t + 2 : t;
            zslot = *reinterpret_cast<const float4*>(zbase + (size_t)tp * 800 + jg * 4);
        }
        if (ga) {
            const int qb = s * 5;
            #pragma unroll
            for (int r2 = 0; r2 < 4; ++r2) {   // one row at a time (reg-lean)
                u64 a0 = 0ull, a1 = 0ull, a2 = 0ull, a3 = 0ull;
                const ulonglong2* hp =
                    reinterpret_cast<const ulonglong2*>(&h_s[cur][r2][0]);
                #pragma unroll
                for (int q = 0; q < 5; ++q) {
                    ulonglong2 hv = hp[qb + q];
                    FMA2(a0, hv.x, w2[2 * q][0], a0);
                    FMA2(a1, hv.x, w2[2 * q][1], a1);
                    FMA2(a2, hv.x, w2[2 * q][2], a2);
                    FMA2(a3, hv.x, w2[2 * q][3], a3);
                    FMA2(a0, hv.y, w2[2 * q + 1][0], a0);
                    FMA2(a1, hv.y, w2[2 * q + 1][1], a1);
                    FMA2(a2, hv.y, w2[2 * q + 1][2], a2);
                    FMA2(a3, hv.y, w2[2 * q + 1][3], a3);
                }
                float2 p0 = unpack2(a0), p1 = unpack2(a1),
                       p2 = unpack2(a2), p3 = unpack2(a3);
                zp[s][r2][jl] = make_float4(p0.x + p0.y, p1.x + p1.y,
                                            p2.x + p2.y, p3.x + p3.y);
            }
        }
        __syncthreads();
        if (red) {
            float z0 = zc.x, z1 = zc.y, z2 = zc.z, z3 = zc.w;
            #pragma unroll
            for (int ss = 0; ss < 10; ++ss) {
                float4 p = zp[ss][rr][jl];
                z0 += p.x; z1 += p.y; z2 += p.z; z3 += p.w;
            }
            float gi = sigm(z0), gf = sigm(z1), gg = tanh_fast(z2), go = sigm(z3);
            c = gf * c + gi * gg;
            float h = go * tanh_fast(c);

            const int nxt = cur ^ 1;
            uint32_t laddr = hs_addr + (uint32_t)((nxt * 4 + rr) * 208 + jg) * 4u;
            #pragma unroll
            for (int p = 0; p < 4; ++p) {
                uint32_t raddr;
                asm("mapa.shared::cluster.u32 %0, %1, %2;"
                    : "=r"(raddr) : "r"(laddr), "r"(p));
                asm volatile("st.shared::cluster.f32 [%0], %1;"
                             :: "r"(raddr), "f"(h) : "memory");
            }
            if (WRITE_Y) ybase[(size_t)t * 200 + jg] = h;
            if (t == TLEN - 1) g_hbuf[b * HPAD + jg] = h;
        }
        asm volatile("barrier.cluster.arrive.aligned;" ::: "memory");
        asm volatile("barrier.cluster.wait.aligned;" ::: "memory");
    };

    for (int t = 0; t < TLEN; t += 2) {
        step(t,     zb0, 0);
        step(t + 1, zb1, 1);
    }
}

// Final dense: out[b, o] = h_last[b, :200] @ Wd + bd.
__global__ void dense_kernel(const float* __restrict__ Wd,
                             const float* __restrict__ bd,
                             float* __restrict__ out)
{
    int idx = blockIdx.x * blockDim.x + threadIdx.x;
    if (idx >= BSZ * 6) return;
    int b = idx / 6, o = idx - b * 6;
    const float* h = g_hbuf + b * HPAD;
    float s = bd[o];
    #pragma unroll 8
    for (int k = 0; k < 200; ++k) s += h[k] * Wd[k * 6 + o];
    out[idx] = s;
}

extern "C" void kernel_launch(void* const* d_in, const int* in_sizes, int n_in,
                              void* d_out, int out_size)
{
    const float* xs  = (const float*)d_in[0];
    const float* Wx0 = (const float*)d_in[1];
    const float* Wh0 = (const float*)d_in[2];
    const float* b0  = (const float*)d_in[3];
    const float* Wx1 = (const float*)d_in[4];
    const float* Wh1 = (const float*)d_in[5];
    const float* b1  = (const float*)d_in[6];
    const float* Wx2 = (const float*)d_in[7];
    const float* Wh2 = (const float*)d_in[8];
    const float* b2  = (const float*)d_in[9];
    const float* Wx3 = (const float*)d_in[10];
    const float* Wh3 = (const float*)d_in[11];
    const float* b3  = (const float*)d_in[12];
    const float* Wd  = (const float*)d_in[13];
    const float* bd  = (const float*)d_in[14];

    const dim3 gN400(4, 1024);
    const dim3 gN800(7, 1024);

    // L0
    gemm_x<128><<<gN400, 256>>>(xs, Wx0, b0, 400, 100, 0);
    scan100<<<BSZ, 512>>>(Wh0);
    // L1
    gemm_x<100><<<gN400, 256>>>(nullptr, Wx1, b1, 400, 100, 1);
    scan100<<<BSZ, 512>>>(Wh1);
    // L2
    gemm_x<100><<<gN800, 256>>>(nullptr, Wx2, b2, 800, 200, 1);
    scan200<1><<<BSZ, 512>>>(Wh2);
    // L3
    gemm_x<200><<<gN800, 256>>>(nullptr, Wx3, b3, 800, 200, 1);
    scan200<0><<<BSZ, 512>>>(Wh3);
    // head
    dense_kernel<<<3, 256>>>(Wd, bd, (float*)d_out);
}